// round 15
// baseline (speedup 1.0000x reference)
#include <cuda_runtime.h>
#include <math.h>
#include <stdint.h>

// Problem constants
#define Bb   4
#define Ssz  4096
#define Dd   2048
#define DFFz 8192
#define KSEL 512
#define MROWS (Bb*KSEL)   // 2048 selected rows

// GEMM tiling: CTA 128x128, TK=16, thread 8x8, 256 threads
#define TK 16
#define STAGES 3
#define STAGE_F32 (2*TK*128)                  // A(16x128) + B(16x128) = 4096 f32
#define SMEM_BYTES (STAGES*STAGE_F32*4)       // 49152

#define COPYB 256                             // copy+router blocks (64 rows each)

// ---------------- scratch (device globals; no runtime allocation) ----------
__device__ __align__(1024) float g_logits[Bb*Ssz];
__device__ __align__(1024) int   g_tokens[MROWS];
__device__ __align__(1024) float g_rw[MROWS];
__device__ int g_done = 0;
__device__ __align__(1024) float g_fxT[(size_t)Dd*MROWS];    // [K=2048][M=2048] 16MB
__device__ __align__(1024) float g_hT [(size_t)DFFz*MROWS];  // [K=8192][M=2048] 64MB

// ---------------- helpers ----------------------------------------------------
__device__ __forceinline__ uint32_t smem_u32(const void* p){
    uint32_t a;
    asm("{ .reg .u64 t; cvta.to.shared.u64 t, %1; cvt.u32.u64 %0, t; }" : "=r"(a) : "l"(p));
    return a;
}
__device__ __forceinline__ unsigned int fmono(float f){
    unsigned int b = __float_as_uint(f);
    return (b & 0x80000000u) ? ~b : (b | 0x80000000u);
}
__device__ __forceinline__ float gelu_exact(float z){
    return 0.5f * z * (1.0f + erff(z * 0.70710678118654752f));
}
__device__ __forceinline__ unsigned long long pack2(float lo, float hi){
    unsigned long long r;
    asm("mov.b64 %0, {%1, %2};" : "=l"(r) : "f"(lo), "f"(hi));
    return r;
}
__device__ __forceinline__ void ffma2(unsigned long long &c, unsigned long long a, unsigned long long b){
    asm("fma.rn.f32x2 %0, %1, %2, %0;" : "+l"(c) : "l"(a), "l"(b));
}
__device__ __forceinline__ float2 unpack2(unsigned long long v){
    float lo, hi;
    asm("mov.b64 {%0, %1}, %2;" : "=f"(lo), "=f"(hi) : "l"(v));
    return make_float2(lo, hi);
}
__device__ __forceinline__ void cp16(uint32_t dst, const void* src){
    asm volatile("cp.async.cg.shared.global [%0], [%1], 16;" :: "r"(dst), "l"(src));
}

// ------ one kernel: blocks 0..3 = top-k sort; blocks 4.. = copy+router -------
__global__ void __launch_bounds__(1024)
topk_copy_router_kernel(const float* __restrict__ x, float* __restrict__ out,
                        const float* __restrict__ Wr, const float* __restrict__ br){
    __shared__ unsigned long long keys[Ssz];
    __shared__ float sval[KSEL];
    __shared__ int   sidx[KSEL];
    __shared__ float red [KSEL];
    int tid = threadIdx.x;

    if (blockIdx.x >= Bb){
        // ---- copy + router blocks: 64 rows each ----
        int rb   = blockIdx.x - Bb;
        int wid  = tid >> 5, lane = tid & 31;
        const float4* w4 = reinterpret_cast<const float4*>(Wr);
        float brv = br[0];
        #pragma unroll
        for (int r = wid; r < 64; r += 32){
            int row = rb*64 + r;
            const float4* xr   = reinterpret_cast<const float4*>(x   + (size_t)row * Dd);
            float4*       orow = reinterpret_cast<float4*>(out + (size_t)row * Dd);
            float s = 0.f;
            #pragma unroll
            for (int q = 0; q < 16; q++){
                int i = lane + q*32;            // 512 float4 per row
                float4 a = xr[i], w = w4[i];
                orow[i] = a;
                s += a.x*w.x + a.y*w.y + a.z*w.z + a.w*w.w;
            }
            #pragma unroll
            for (int o = 16; o > 0; o >>= 1) s += __shfl_down_sync(0xffffffffu, s, o);
            if (lane == 0) g_logits[row] = s + brv;
        }
        __syncthreads();
        __threadfence();
        if (tid == 0) atomicAdd(&g_done, 64);
        return;
    }

    // ---- top-k blocks: wait for all logits from copy blocks ----
    if (tid == 0){
        while (atomicAdd(&g_done, 0) < Bb*Ssz) __nanosleep(200);
    }
    __syncthreads();       // block-wide barrier + memory fence for the block

    int b = blockIdx.x;
    for (int s = tid; s < Ssz; s += blockDim.x){
        unsigned int m = fmono(g_logits[b*Ssz + s]);
        keys[s] = ((unsigned long long)m << 32) | (unsigned int)(~(unsigned int)s);
    }
    __syncthreads();
    for (int k = 2; k <= Ssz; k <<= 1){
        for (int j = k >> 1; j > 0; j >>= 1){
            for (int t = tid; t < Ssz; t += blockDim.x){
                int ixj = t ^ j;
                if (ixj > t){
                    bool up = ((t & k) == 0);
                    unsigned long long a = keys[t], c = keys[ixj];
                    bool sw = up ? (a > c) : (a < c);
                    if (sw){ keys[t] = c; keys[ixj] = a; }
                }
            }
            __syncthreads();
        }
    }
    if (tid < KSEL){
        unsigned long long key = keys[Ssz - 1 - tid];
        unsigned int u = (unsigned int)(key >> 32);
        float v = (u & 0x80000000u) ? __uint_as_float(u & 0x7FFFFFFFu)
                                    : __uint_as_float(~u);
        sval[tid] = v;
        sidx[tid] = (int)(~(unsigned int)key);
    }
    __syncthreads();
    float vmax = sval[0];
    if (tid < KSEL) red[tid] = expf(sval[tid] - vmax);
    __syncthreads();
    for (int st = KSEL/2; st > 0; st >>= 1){
        if (tid < st) red[tid] += red[tid + st];
        __syncthreads();
    }
    float denom = red[0];
    if (tid < KSEL){
        g_tokens[b*KSEL + tid] = sidx[tid];
        g_rw   [b*KSEL + tid] = expf(sval[tid] - vmax) / denom;
    }
}

// ---------------- gather selected rows into FX^T [K][M] ----------------------
__global__ void gatherT_kernel(const float* __restrict__ x){
    __shared__ float t[32][33];
    // deterministic reset of the copy/router completion counter for next replay
    if (blockIdx.x == 0 && blockIdx.y == 0 && threadIdx.x == 0) g_done = 0;
    int m0 = blockIdx.x * 32;
    int k0 = blockIdx.y * 32;
    int tx = threadIdx.x & 31, ty = threadIdx.x >> 5;   // 32x8
    #pragma unroll
    for (int r = 0; r < 4; r++){
        int m = m0 + ty + 8*r;
        int b = m >> 9;
        int tok = g_tokens[m];
        t[ty + 8*r][tx] = x[((size_t)b*Ssz + tok)*Dd + k0 + tx];
    }
    __syncthreads();
    #pragma unroll
    for (int r = 0; r < 4; r++)
        g_fxT[(size_t)(k0 + ty + 8*r) * MROWS + m0 + tx] = t[tx][ty + 8*r];
}

// ---------------- f32x2 SIMT GEMM, 8x8 thread tile (champion loop) ------------
// A^T: [K][M], B: [K][N]
// EPI==1: g_hT[n][m] = gelu(sum + b1[n])                 (K=Dd,  N=DFFz)
// EPI==2: out[b,tok(m),n] = x[...] + rw[m]*(sum + b2[n]) (K=DFFz, N=Dd)
template<int EPI>
__global__ void __launch_bounds__(256, 2)
gemm_kernel(const float* __restrict__ AT, const float* __restrict__ Bw,
            const float* __restrict__ bias,
            const float* __restrict__ xin, float* __restrict__ out,
            int M, int N, int K)
{
    extern __shared__ float sm[];
    const int tid = threadIdx.x;
    const int tx = tid & 15, ty = tid >> 4;
    const int bn = blockIdx.x, bm = blockIdx.y;
    const uint32_t sbase = smem_u32(sm);
    const int KT = K / TK;

    const float* Ag = AT + bm * 128;    // + k*M
    const float* Bg = Bw + bn * 128;    // + k*N

    unsigned long long acc[8][4];
    #pragma unroll
    for (int i = 0; i < 8; i++)
        #pragma unroll
        for (int j = 0; j < 4; j++) acc[i][j] = 0ull;

    auto ld_stage = [&](int kt, int s){
        uint32_t base = sbase + (uint32_t)(s * STAGE_F32) * 4;
        {   // A: 16 rows x 128 f32 = 512 16B chunks
            int ch = tid;
            #pragma unroll
            for (int i = 0; i < 2; i++, ch += 256){
                int kl = ch >> 5, mc = ch & 31;
                cp16(base + (uint32_t)(kl*128 + mc*4)*4,
                     Ag + (size_t)(kt*TK + kl)*M + mc*4);
            }
        }
        {   // B
            uint32_t bb = base + (uint32_t)(TK*128)*4;
            int ch = tid;
            #pragma unroll
            for (int i = 0; i < 2; i++, ch += 256){
                int kl = ch >> 5, nc = ch & 31;
                cp16(bb + (uint32_t)(kl*128 + nc*4)*4,
                     Bg + (size_t)(kt*TK + kl)*N + nc*4);
            }
        }
        asm volatile("cp.async.commit_group;" ::: "memory");
    };

    ld_stage(0, 0);
    ld_stage(1, 1);

    int s = 0;
    for (int kt = 0; kt < KT; kt++){
        if (kt == KT - 1) asm volatile("cp.async.wait_group 0;" ::: "memory");
        else              asm volatile("cp.async.wait_group 1;" ::: "memory");
        __syncthreads();
        if (kt + 2 < KT){
            int s2 = s + 2; if (s2 >= STAGES) s2 -= STAGES;
            ld_stage(kt + 2, s2);
        }

        const float* As = sm + s * STAGE_F32;
        const float* Bs = As + TK*128;

        // preload kk=0 fragments
        float4 a0 = *reinterpret_cast<const float4*>(As + ty*8);
        float4 a1 = *reinterpret_cast<const float4*>(As + ty*8 + 4);
        const unsigned long long* bq0 =
            reinterpret_cast<const unsigned long long*>(Bs + tx*4);
        const unsigned long long* bq1 =
            reinterpret_cast<const unsigned long long*>(Bs + tx*4 + 64);
        unsigned long long b0 = bq0[0], b1 = bq0[1], b2 = bq1[0], b3 = bq1[1];

        #pragma unroll
        for (int kk = 0; kk < TK; kk++){
            float4 na0, na1;
            unsigned long long nb0, nb1, nb2, nb3;
            if (kk + 1 < TK){
                const float* Ar = As + (kk+1)*128;
                const float* Br = Bs + (kk+1)*128;
                na0 = *reinterpret_cast<const float4*>(Ar + ty*8);
                na1 = *reinterpret_cast<const float4*>(Ar + ty*8 + 4);
                const unsigned long long* p0 =
                    reinterpret_cast<const unsigned long long*>(Br + tx*4);
                const unsigned long long* p1 =
                    reinterpret_cast<const unsigned long long*>(Br + tx*4 + 64);
                nb0 = p0[0]; nb1 = p0[1]; nb2 = p1[0]; nb3 = p1[1];
            }
            float av[8] = {a0.x, a0.y, a0.z, a0.w, a1.x, a1.y, a1.z, a1.w};
            #pragma unroll
            for (int i = 0; i < 8; i++){
                unsigned long long ap = pack2(av[i], av[i]);
                ffma2(acc[i][0], ap, b0);
                ffma2(acc[i][1], ap, b1);
                ffma2(acc[i][2], ap, b2);
                ffma2(acc[i][3], ap, b3);
            }
            if (kk + 1 < TK){
                a0 = na0; a1 = na1;
                b0 = nb0; b1 = nb1; b2 = nb2; b3 = nb3;
            }
        }
        s++; if (s >= STAGES) s = 0;
    }

    // ---------------- epilogue ----------------
    const int m0 = bm*128 + ty*8;
    const int n0a = bn*128 + tx*4;      // cols n0a..+3 and n0a+64..+67
    float bva[4], bvb[4];
    #pragma unroll
    for (int c = 0; c < 4; c++){ bva[c] = bias[n0a + c]; bvb[c] = bias[n0a + 64 + c]; }

    if (EPI == 1){
        #pragma unroll
        for (int p = 0; p < 4; p++){
            #pragma unroll
            for (int h = 0; h < 2; h++){
                int n = (p < 2) ? (n0a + p*2 + h) : (n0a + 64 + (p-2)*2 + h);
                float bb = (p < 2) ? bva[p*2 + h] : bvb[(p-2)*2 + h];
                float v[8];
                #pragma unroll
                for (int i = 0; i < 8; i++){
                    float2 u = unpack2(acc[i][p]);
                    v[i] = gelu_exact((h ? u.y : u.x) + bb);
                }
                float* dst = g_hT + (size_t)n * MROWS + m0;
                *reinterpret_cast<float4*>(dst)     = make_float4(v[0], v[1], v[2], v[3]);
                *reinterpret_cast<float4*>(dst + 4) = make_float4(v[4], v[5], v[6], v[7]);
            }
        }
    } else {
        #pragma unroll
        for (int i = 0; i < 8; i++){
            int m = m0 + i;
            int bb = m >> 9;
            int tok = g_tokens[m];
            float w = g_rw[m];
            size_t base = ((size_t)bb * Ssz + tok) * (size_t)Dd;
            float2 q0 = unpack2(acc[i][0]), q1 = unpack2(acc[i][1]);
            float2 q2 = unpack2(acc[i][2]), q3 = unpack2(acc[i][3]);
            const float4 xa = *reinterpret_cast<const float4*>(xin + base + n0a);
            const float4 xb = *reinterpret_cast<const float4*>(xin + base + n0a + 64);
            float4 oa, ob;
            oa.x = xa.x + w*(q0.x + bva[0]);  oa.y = xa.y + w*(q0.y + bva[1]);
            oa.z = xa.z + w*(q1.x + bva[2]);  oa.w = xa.w + w*(q1.y + bva[3]);
            ob.x = xb.x + w*(q2.x + bvb[0]);  ob.y = xb.y + w*(q2.y + bvb[1]);
            ob.z = xb.z + w*(q3.x + bvb[2]);  ob.w = xb.w + w*(q3.y + bvb[3]);
            *reinterpret_cast<float4*>(out + base + n0a)      = oa;
            *reinterpret_cast<float4*>(out + base + n0a + 64) = ob;
        }
    }
}

// ---------------- launch -------------------------------------------------------
extern "C" void kernel_launch(void* const* d_in, const int* in_sizes, int n_in,
                              void* d_out, int out_size){
    const float* x  = (const float*)d_in[0];
    const float* Wr = (const float*)d_in[1];
    const float* br = (const float*)d_in[2];
    const float* W1 = (const float*)d_in[3];
    const float* b1 = (const float*)d_in[4];
    const float* W2 = (const float*)d_in[5];
    const float* b2 = (const float*)d_in[6];
    float* out = (float*)d_out;

    cudaFuncSetAttribute(gemm_kernel<1>, cudaFuncAttributeMaxDynamicSharedMemorySize, SMEM_BYTES);
    cudaFuncSetAttribute(gemm_kernel<2>, cudaFuncAttributeMaxDynamicSharedMemorySize, SMEM_BYTES);

    // one kernel: copy x->out + router logits (blocks 4..259) + top-k (blocks 0..3)
    topk_copy_router_kernel<<<Bb + COPYB, 1024>>>(x, out, Wr, br);
    gatherT_kernel<<<dim3(MROWS/32, Dd/32), 256>>>(x);   // also resets g_done

    float *p_fxT, *p_hT;
    cudaGetSymbolAddress((void**)&p_fxT, g_fxT);
    cudaGetSymbolAddress((void**)&p_hT,  g_hT);

    gemm_kernel<1><<<dim3(DFFz/128, MROWS/128), 256, SMEM_BYTES>>>(
        p_fxT, W1, b1, nullptr, nullptr, MROWS, DFFz, Dd);
    gemm_kernel<2><<<dim3(Dd/128, MROWS/128), 256, SMEM_BYTES>>>(
        p_hT, W2, b2, x, out, MROWS, Dd, DFFz);
}

// round 16
// speedup vs baseline: 1.0188x; 1.0188x over previous
#include <cuda_runtime.h>
#include <math.h>
#include <stdint.h>

// Problem constants
#define Bb   4
#define Ssz  4096
#define Dd   2048
#define DFFz 8192
#define KSEL 512
#define MROWS (Bb*KSEL)   // 2048 selected rows

// GEMM tiling: CTA 128x128, TK=16, thread 8x8, 256 threads
#define TK 16
#define STAGES 3
#define STAGE_F32 (2*TK*128)                  // A(16x128) + B(16x128) = 4096 f32
#define SMEM_BYTES (STAGES*STAGE_F32*4)       // 49152

#define COPYB 252                             // copy blocks appended to topk grid
#define SPLITK 2                              // GEMM2 K-split

// ---------------- scratch (device globals; no runtime allocation) ----------
__device__ __align__(1024) float g_logits[Bb*Ssz];
__device__ __align__(1024) int   g_tokens[MROWS];
__device__ __align__(1024) float g_rw[MROWS];
__device__ __align__(1024) float g_fxT[(size_t)Dd*MROWS];    // [K=2048][M=2048] 16MB
__device__ __align__(1024) float g_hT [(size_t)DFFz*MROWS];  // [K=8192][M=2048] 64MB
__device__ __align__(1024) float g_part[(size_t)SPLITK*MROWS*Dd]; // 33.5MB partials

// ---------------- helpers ----------------------------------------------------
__device__ __forceinline__ uint32_t smem_u32(const void* p){
    uint32_t a;
    asm("{ .reg .u64 t; cvta.to.shared.u64 t, %1; cvt.u32.u64 %0, t; }" : "=r"(a) : "l"(p));
    return a;
}
__device__ __forceinline__ unsigned int fmono(float f){
    unsigned int b = __float_as_uint(f);
    return (b & 0x80000000u) ? ~b : (b | 0x80000000u);
}
__device__ __forceinline__ float gelu_exact(float z){
    return 0.5f * z * (1.0f + erff(z * 0.70710678118654752f));
}
__device__ __forceinline__ unsigned long long pack2(float lo, float hi){
    unsigned long long r;
    asm("mov.b64 %0, {%1, %2};" : "=l"(r) : "f"(lo), "f"(hi));
    return r;
}
__device__ __forceinline__ void ffma2(unsigned long long &c, unsigned long long a, unsigned long long b){
    asm("fma.rn.f32x2 %0, %1, %2, %0;" : "+l"(c) : "l"(a), "l"(b));
}
__device__ __forceinline__ float2 unpack2(unsigned long long v){
    float lo, hi;
    asm("mov.b64 {%0, %1}, %2;" : "=f"(lo), "=f"(hi) : "l"(v));
    return make_float2(lo, hi);
}
__device__ __forceinline__ void cp16(uint32_t dst, const void* src){
    asm volatile("cp.async.cg.shared.global [%0], [%1], 16;" :: "r"(dst), "l"(src));
}

// ---------------- router (logits only) ---------------------------------------
__global__ void router_kernel(const float* __restrict__ x,
                              const float* __restrict__ Wr,
                              const float* __restrict__ br){
    int row  = blockIdx.x * (blockDim.x >> 5) + (threadIdx.x >> 5);
    int lane = threadIdx.x & 31;
    const float4* xr = reinterpret_cast<const float4*>(x + (size_t)row * Dd);
    const float4* w4 = reinterpret_cast<const float4*>(Wr);
    float s = 0.f;
    #pragma unroll 4
    for (int i = lane; i < Dd/4; i += 32){
        float4 a = xr[i], w = w4[i];
        s += a.x*w.x + a.y*w.y + a.z*w.z + a.w*w.w;
    }
    #pragma unroll
    for (int o = 16; o > 0; o >>= 1) s += __shfl_down_sync(0xffffffffu, s, o);
    if (lane == 0) g_logits[row] = s + br[0];
}

// ---------------- top-k (blocks 0..3) + x->out copy (blocks 4..) -------------
__global__ void topk_copy_kernel(const float* __restrict__ x,
                                 float* __restrict__ out){
    __shared__ unsigned long long keys[Ssz];
    __shared__ float sval[KSEL];
    __shared__ int   sidx[KSEL];
    __shared__ float red [KSEL];
    int tid = threadIdx.x;

    if (blockIdx.x >= Bb){
        const float4* xs = reinterpret_cast<const float4*>(x);
        float4*       os = reinterpret_cast<float4*>(out);
        const long long N4 = (long long)Bb * Ssz * Dd / 4;
        for (long long i = (long long)(blockIdx.x - Bb) * blockDim.x + tid;
             i < N4; i += (long long)COPYB * blockDim.x)
            os[i] = xs[i];
        return;
    }

    int b = blockIdx.x;
    for (int s = tid; s < Ssz; s += blockDim.x){
        unsigned int m = fmono(g_logits[b*Ssz + s]);
        keys[s] = ((unsigned long long)m << 32) | (unsigned int)(~(unsigned int)s);
    }
    __syncthreads();
    for (int k = 2; k <= Ssz; k <<= 1){
        for (int j = k >> 1; j > 0; j >>= 1){
            for (int t = tid; t < Ssz; t += blockDim.x){
                int ixj = t ^ j;
                if (ixj > t){
                    bool up = ((t & k) == 0);
                    unsigned long long a = keys[t], c = keys[ixj];
                    bool sw = up ? (a > c) : (a < c);
                    if (sw){ keys[t] = c; keys[ixj] = a; }
                }
            }
            __syncthreads();
        }
    }
    if (tid < KSEL){
        unsigned long long key = keys[Ssz - 1 - tid];
        unsigned int u = (unsigned int)(key >> 32);
        float v = (u & 0x80000000u) ? __uint_as_float(u & 0x7FFFFFFFu)
                                    : __uint_as_float(~u);
        sval[tid] = v;
        sidx[tid] = (int)(~(unsigned int)key);
    }
    __syncthreads();
    float vmax = sval[0];
    if (tid < KSEL) red[tid] = expf(sval[tid] - vmax);
    __syncthreads();
    for (int st = KSEL/2; st > 0; st >>= 1){
        if (tid < st) red[tid] += red[tid + st];
        __syncthreads();
    }
    float denom = red[0];
    if (tid < KSEL){
        g_tokens[b*KSEL + tid] = sidx[tid];
        g_rw   [b*KSEL + tid] = expf(sval[tid] - vmax) / denom;
    }
}

// ---------------- gather selected rows into FX^T [K][M] ----------------------
__global__ void gatherT_kernel(const float* __restrict__ x){
    __shared__ float t[32][33];
    int m0 = blockIdx.x * 32;
    int k0 = blockIdx.y * 32;
    int tx = threadIdx.x & 31, ty = threadIdx.x >> 5;   // 32x8
    #pragma unroll
    for (int r = 0; r < 4; r++){
        int m = m0 + ty + 8*r;
        int b = m >> 9;
        int tok = g_tokens[m];
        t[ty + 8*r][tx] = x[((size_t)b*Ssz + tok)*Dd + k0 + tx];
    }
    __syncthreads();
    #pragma unroll
    for (int r = 0; r < 4; r++)
        g_fxT[(size_t)(k0 + ty + 8*r) * MROWS + m0 + tx] = t[tx][ty + 8*r];
}

// ---------------- f32x2 SIMT GEMM (champion loop, optional K-split) -----------
// A^T: [K][M], B: [K][N].  blockIdx.z = K-split index (gridDim.z splits).
// EPI==1: g_hT[n][m] = gelu(sum + b1[n])          (K=Dd, N=DFFz, z=1)
// EPI==2: g_part[z][m][n] = raw partial sum        (K=DFFz, N=Dd, z=SPLITK)
template<int EPI>
__global__ void __launch_bounds__(256, 2)
gemm_kernel(const float* __restrict__ AT, const float* __restrict__ Bw,
            const float* __restrict__ bias,
            int M, int N, int K)
{
    extern __shared__ float sm[];
    const int tid = threadIdx.x;
    const int tx = tid & 15, ty = tid >> 4;
    const int bn = blockIdx.x, bm = blockIdx.y;
    const uint32_t sbase = smem_u32(sm);
    const int kchunk = K / gridDim.z;
    const int KT = kchunk / TK;
    const int kofs = blockIdx.z * kchunk;

    const float* Ag = AT + (size_t)kofs * M + bm * 128;   // + k*M
    const float* Bg = Bw + (size_t)kofs * N + bn * 128;   // + k*N

    unsigned long long acc[8][4];
    #pragma unroll
    for (int i = 0; i < 8; i++)
        #pragma unroll
        for (int j = 0; j < 4; j++) acc[i][j] = 0ull;

    auto ld_stage = [&](int kt, int s){
        uint32_t base = sbase + (uint32_t)(s * STAGE_F32) * 4;
        {   // A: 16 rows x 128 f32 = 512 16B chunks
            int ch = tid;
            #pragma unroll
            for (int i = 0; i < 2; i++, ch += 256){
                int kl = ch >> 5, mc = ch & 31;
                cp16(base + (uint32_t)(kl*128 + mc*4)*4,
                     Ag + (size_t)(kt*TK + kl)*M + mc*4);
            }
        }
        {   // B
            uint32_t bb = base + (uint32_t)(TK*128)*4;
            int ch = tid;
            #pragma unroll
            for (int i = 0; i < 2; i++, ch += 256){
                int kl = ch >> 5, nc = ch & 31;
                cp16(bb + (uint32_t)(kl*128 + nc*4)*4,
                     Bg + (size_t)(kt*TK + kl)*N + nc*4);
            }
        }
        asm volatile("cp.async.commit_group;" ::: "memory");
    };

    ld_stage(0, 0);
    ld_stage(1, 1);

    int s = 0;
    for (int kt = 0; kt < KT; kt++){
        if (kt == KT - 1) asm volatile("cp.async.wait_group 0;" ::: "memory");
        else              asm volatile("cp.async.wait_group 1;" ::: "memory");
        __syncthreads();
        if (kt + 2 < KT){
            int s2 = s + 2; if (s2 >= STAGES) s2 -= STAGES;
            ld_stage(kt + 2, s2);
        }

        const float* As = sm + s * STAGE_F32;
        const float* Bs = As + TK*128;

        // preload kk=0 fragments
        float4 a0 = *reinterpret_cast<const float4*>(As + ty*8);
        float4 a1 = *reinterpret_cast<const float4*>(As + ty*8 + 4);
        const unsigned long long* bq0 =
            reinterpret_cast<const unsigned long long*>(Bs + tx*4);
        const unsigned long long* bq1 =
            reinterpret_cast<const unsigned long long*>(Bs + tx*4 + 64);
        unsigned long long b0 = bq0[0], b1 = bq0[1], b2 = bq1[0], b3 = bq1[1];

        #pragma unroll
        for (int kk = 0; kk < TK; kk++){
            float4 na0, na1;
            unsigned long long nb0, nb1, nb2, nb3;
            if (kk + 1 < TK){
                const float* Ar = As + (kk+1)*128;
                const float* Br = Bs + (kk+1)*128;
                na0 = *reinterpret_cast<const float4*>(Ar + ty*8);
                na1 = *reinterpret_cast<const float4*>(Ar + ty*8 + 4);
                const unsigned long long* p0 =
                    reinterpret_cast<const unsigned long long*>(Br + tx*4);
                const unsigned long long* p1 =
                    reinterpret_cast<const unsigned long long*>(Br + tx*4 + 64);
                nb0 = p0[0]; nb1 = p0[1]; nb2 = p1[0]; nb3 = p1[1];
            }
            float av[8] = {a0.x, a0.y, a0.z, a0.w, a1.x, a1.y, a1.z, a1.w};
            #pragma unroll
            for (int i = 0; i < 8; i++){
                unsigned long long ap = pack2(av[i], av[i]);
                ffma2(acc[i][0], ap, b0);
                ffma2(acc[i][1], ap, b1);
                ffma2(acc[i][2], ap, b2);
                ffma2(acc[i][3], ap, b3);
            }
            if (kk + 1 < TK){
                a0 = na0; a1 = na1;
                b0 = nb0; b1 = nb1; b2 = nb2; b3 = nb3;
            }
        }
        s++; if (s >= STAGES) s = 0;
    }

    // ---------------- epilogue ----------------
    const int m0 = bm*128 + ty*8;
    const int n0a = bn*128 + tx*4;      // cols n0a..+3 and n0a+64..+67

    if (EPI == 1){
        float bva[4], bvb[4];
        #pragma unroll
        for (int c = 0; c < 4; c++){ bva[c] = bias[n0a + c]; bvb[c] = bias[n0a + 64 + c]; }
        #pragma unroll
        for (int p = 0; p < 4; p++){
            #pragma unroll
            for (int h = 0; h < 2; h++){
                int n = (p < 2) ? (n0a + p*2 + h) : (n0a + 64 + (p-2)*2 + h);
                float bb = (p < 2) ? bva[p*2 + h] : bvb[(p-2)*2 + h];
                float v[8];
                #pragma unroll
                for (int i = 0; i < 8; i++){
                    float2 u = unpack2(acc[i][p]);
                    v[i] = gelu_exact((h ? u.y : u.x) + bb);
                }
                float* dst = g_hT + (size_t)n * MROWS + m0;
                *reinterpret_cast<float4*>(dst)     = make_float4(v[0], v[1], v[2], v[3]);
                *reinterpret_cast<float4*>(dst + 4) = make_float4(v[4], v[5], v[6], v[7]);
            }
        }
    } else {
        // raw partial sums -> g_part[z][m][n]
        float* pb = g_part + (size_t)blockIdx.z * MROWS * Dd;
        #pragma unroll
        for (int i = 0; i < 8; i++){
            int m = m0 + i;
            float2 q0 = unpack2(acc[i][0]), q1 = unpack2(acc[i][1]);
            float2 q2 = unpack2(acc[i][2]), q3 = unpack2(acc[i][3]);
            float* dst = pb + (size_t)m * Dd;
            *reinterpret_cast<float4*>(dst + n0a)      = make_float4(q0.x, q0.y, q1.x, q1.y);
            *reinterpret_cast<float4*>(dst + n0a + 64) = make_float4(q2.x, q2.y, q3.x, q3.y);
        }
    }
}

// ---------------- reduce partials + bias + weight + scatter-add --------------
__global__ void __launch_bounds__(512)
reduce2_kernel(const float* __restrict__ xin, const float* __restrict__ b2,
               float* __restrict__ out){
    int m = blockIdx.x;
    int i = threadIdx.x;                       // 512 threads x float4 = 2048 cols
    int b = m >> 9;
    int tok = g_tokens[m];
    float w = g_rw[m];
    size_t base = ((size_t)b * Ssz + tok) * (size_t)Dd;
    const float4 p0 = reinterpret_cast<const float4*>(g_part + (size_t)m * Dd)[i];
    const float4 p1 = reinterpret_cast<const float4*>(g_part + (size_t)MROWS*Dd + (size_t)m * Dd)[i];
    const float4 xv = reinterpret_cast<const float4*>(xin + base)[i];
    const float4 bv = reinterpret_cast<const float4*>(b2)[i];
    float4 o;
    o.x = xv.x + w * (p0.x + p1.x + bv.x);
    o.y = xv.y + w * (p0.y + p1.y + bv.y);
    o.z = xv.z + w * (p0.z + p1.z + bv.z);
    o.w = xv.w + w * (p0.w + p1.w + bv.w);
    reinterpret_cast<float4*>(out + base)[i] = o;
}

// ---------------- launch -------------------------------------------------------
extern "C" void kernel_launch(void* const* d_in, const int* in_sizes, int n_in,
                              void* d_out, int out_size){
    const float* x  = (const float*)d_in[0];
    const float* Wr = (const float*)d_in[1];
    const float* br = (const float*)d_in[2];
    const float* W1 = (const float*)d_in[3];
    const float* b1 = (const float*)d_in[4];
    const float* W2 = (const float*)d_in[5];
    const float* b2 = (const float*)d_in[6];
    float* out = (float*)d_out;

    cudaFuncSetAttribute(gemm_kernel<1>, cudaFuncAttributeMaxDynamicSharedMemorySize, SMEM_BYTES);
    cudaFuncSetAttribute(gemm_kernel<2>, cudaFuncAttributeMaxDynamicSharedMemorySize, SMEM_BYTES);

    router_kernel<<<(Bb*Ssz)/8, 256>>>(x, Wr, br);
    topk_copy_kernel<<<Bb + COPYB, 1024>>>(x, out);   // topk + hidden x->out copy
    gatherT_kernel<<<dim3(MROWS/32, Dd/32), 256>>>(x);

    float *p_fxT, *p_hT;
    cudaGetSymbolAddress((void**)&p_fxT, g_fxT);
    cudaGetSymbolAddress((void**)&p_hT,  g_hT);

    gemm_kernel<1><<<dim3(DFFz/128, MROWS/128, 1), 256, SMEM_BYTES>>>(
        p_fxT, W1, b1, MROWS, DFFz, Dd);
    gemm_kernel<2><<<dim3(Dd/128, MROWS/128, SPLITK), 256, SMEM_BYTES>>>(
        p_hT, W2, b2, MROWS, Dd, DFFz);
    reduce2_kernel<<<MROWS, 512>>>(x, b2, out);
}

// round 17
// speedup vs baseline: 1.0449x; 1.0256x over previous
#include <cuda_runtime.h>
#include <math.h>
#include <stdint.h>

// Problem constants
#define Bb   4
#define Ssz  4096
#define Dd   2048
#define DFFz 8192
#define KSEL 512
#define MROWS (Bb*KSEL)   // 2048 selected rows

// GEMM tiling: CTA 128x128, TK=16, thread 8x8, 256 threads, stream-K
#define TK 16
#define STAGES 3
#define STAGE_F32 (2*TK*128)                  // A(16x128) + B(16x128) = 4096 f32
#define SMEM_BYTES (STAGES*STAGE_F32*4)       // 49152

#define COPYB 252                             // copy blocks appended to topk grid
#define PGRID 304                             // 152 SMs x 2 CTAs, all co-resident

// ---------------- scratch (device globals; no runtime allocation) ----------
__device__ __align__(1024) float g_logits[Bb*Ssz];
__device__ __align__(1024) int   g_tokens[MROWS];
__device__ __align__(1024) float g_rw[MROWS];
__device__ __align__(1024) float g_fxT[(size_t)Dd*MROWS];    // [K=2048][M=2048] 16MB
__device__ __align__(1024) float g_hT [(size_t)DFFz*MROWS];  // [K=8192][M=2048] 64MB
__device__ __align__(1024) float g_ws [(size_t)PGRID*64*256]; // stream-K partials ~20MB
__device__ int g_cnt1[1024];
__device__ int g_cnt2[256];

// ---------------- helpers ----------------------------------------------------
__device__ __forceinline__ uint32_t smem_u32(const void* p){
    uint32_t a;
    asm("{ .reg .u64 t; cvta.to.shared.u64 t, %1; cvt.u32.u64 %0, t; }" : "=r"(a) : "l"(p));
    return a;
}
__device__ __forceinline__ unsigned int fmono(float f){
    unsigned int b = __float_as_uint(f);
    return (b & 0x80000000u) ? ~b : (b | 0x80000000u);
}
__device__ __forceinline__ float gelu_exact(float z){
    return 0.5f * z * (1.0f + erff(z * 0.70710678118654752f));
}
__device__ __forceinline__ unsigned long long pack2(float lo, float hi){
    unsigned long long r;
    asm("mov.b64 %0, {%1, %2};" : "=l"(r) : "f"(lo), "f"(hi));
    return r;
}
__device__ __forceinline__ void ffma2(unsigned long long &c, unsigned long long a, unsigned long long b){
    asm("fma.rn.f32x2 %0, %1, %2, %0;" : "+l"(c) : "l"(a), "l"(b));
}
__device__ __forceinline__ float2 unpack2(unsigned long long v){
    float lo, hi;
    asm("mov.b64 {%0, %1}, %2;" : "=f"(lo), "=f"(hi) : "l"(v));
    return make_float2(lo, hi);
}
__device__ __forceinline__ void cp16(uint32_t dst, const void* src){
    asm volatile("cp.async.cg.shared.global [%0], [%1], 16;" :: "r"(dst), "l"(src));
}

// ---------------- router (logits only) ---------------------------------------
__global__ void router_kernel(const float* __restrict__ x,
                              const float* __restrict__ Wr,
                              const float* __restrict__ br){
    int row  = blockIdx.x * (blockDim.x >> 5) + (threadIdx.x >> 5);
    int lane = threadIdx.x & 31;
    const float4* xr = reinterpret_cast<const float4*>(x + (size_t)row * Dd);
    const float4* w4 = reinterpret_cast<const float4*>(Wr);
    float s = 0.f;
    #pragma unroll 4
    for (int i = lane; i < Dd/4; i += 32){
        float4 a = xr[i], w = w4[i];
        s += a.x*w.x + a.y*w.y + a.z*w.z + a.w*w.w;
    }
    #pragma unroll
    for (int o = 16; o > 0; o >>= 1) s += __shfl_down_sync(0xffffffffu, s, o);
    if (lane == 0) g_logits[row] = s + br[0];
}

// ---------------- top-k (blocks 0..3) + x->out copy (blocks 4..) -------------
__global__ void topk_copy_kernel(const float* __restrict__ x,
                                 float* __restrict__ out){
    __shared__ unsigned long long keys[Ssz];
    __shared__ float sval[KSEL];
    __shared__ int   sidx[KSEL];
    __shared__ float red [KSEL];
    int tid = threadIdx.x;

    if (blockIdx.x >= Bb){
        const float4* xs = reinterpret_cast<const float4*>(x);
        float4*       os = reinterpret_cast<float4*>(out);
        const long long N4 = (long long)Bb * Ssz * Dd / 4;
        for (long long i = (long long)(blockIdx.x - Bb) * blockDim.x + tid;
             i < N4; i += (long long)COPYB * blockDim.x)
            os[i] = xs[i];
        return;
    }

    int b = blockIdx.x;
    for (int s = tid; s < Ssz; s += blockDim.x){
        unsigned int m = fmono(g_logits[b*Ssz + s]);
        keys[s] = ((unsigned long long)m << 32) | (unsigned int)(~(unsigned int)s);
    }
    __syncthreads();
    for (int k = 2; k <= Ssz; k <<= 1){
        for (int j = k >> 1; j > 0; j >>= 1){
            for (int t = tid; t < Ssz; t += blockDim.x){
                int ixj = t ^ j;
                if (ixj > t){
                    bool up = ((t & k) == 0);
                    unsigned long long a = keys[t], c = keys[ixj];
                    bool sw = up ? (a > c) : (a < c);
                    if (sw){ keys[t] = c; keys[ixj] = a; }
                }
            }
            __syncthreads();
        }
    }
    if (tid < KSEL){
        unsigned long long key = keys[Ssz - 1 - tid];
        unsigned int u = (unsigned int)(key >> 32);
        float v = (u & 0x80000000u) ? __uint_as_float(u & 0x7FFFFFFFu)
                                    : __uint_as_float(~u);
        sval[tid] = v;
        sidx[tid] = (int)(~(unsigned int)key);
    }
    __syncthreads();
    float vmax = sval[0];
    if (tid < KSEL) red[tid] = expf(sval[tid] - vmax);
    __syncthreads();
    for (int st = KSEL/2; st > 0; st >>= 1){
        if (tid < st) red[tid] += red[tid + st];
        __syncthreads();
    }
    float denom = red[0];
    if (tid < KSEL){
        g_tokens[b*KSEL + tid] = sidx[tid];
        g_rw   [b*KSEL + tid] = expf(sval[tid] - vmax) / denom;
    }
}

// ---------------- gather selected rows into FX^T [K][M] (+ cnt reset) --------
__global__ void gatherT_kernel(const float* __restrict__ x){
    __shared__ float t[32][33];
    if (blockIdx.x == 0 && blockIdx.y == 0){
        for (int i = threadIdx.x; i < 1024; i += 256) g_cnt1[i] = 0;
        for (int i = threadIdx.x; i < 256;  i += 256) g_cnt2[i] = 0;
    }
    int m0 = blockIdx.x * 32;
    int k0 = blockIdx.y * 32;
    int tx = threadIdx.x & 31, ty = threadIdx.x >> 5;   // 32x8
    #pragma unroll
    for (int r = 0; r < 4; r++){
        int m = m0 + ty + 8*r;
        int b = m >> 9;
        int tok = g_tokens[m];
        t[ty + 8*r][tx] = x[((size_t)b*Ssz + tok)*Dd + k0 + tx];
    }
    __syncthreads();
    #pragma unroll
    for (int r = 0; r < 4; r++)
        g_fxT[(size_t)(k0 + ty + 8*r) * MROWS + m0 + tx] = t[tx][ty + 8*r];
}

// ---------------- stream-K f32x2 SIMT GEMM (champion inner loop) --------------
// A^T: [K][M], B: [K][N]. 304 persistent CTAs over flattened (tile, kchunk) units.
// EPI==1: g_hT[n][m] = gelu(sum + b1[n])                 (K=Dd,  N=DFFz)
// EPI==2: out[b,tok(m),n] = x[...] + rw[m]*(sum + b2[n]) (K=DFFz, N=Dd)
template<int EPI>
__global__ void __launch_bounds__(256, 2)
gemm_kernel(const float* __restrict__ AT, const float* __restrict__ Bw,
            const float* __restrict__ bias,
            const float* __restrict__ xin, float* __restrict__ out,
            int M, int N, int K)
{
    extern __shared__ float sm[];
    const int tid = threadIdx.x;
    const int tx = tid & 15, ty = tid >> 4;
    const uint32_t sbase = smem_u32(sm);
    const int KTt = K / TK;                    // chunks per tile
    const int ntm = M >> 7;
    const int ntiles = ntm * (N >> 7);
    const long long Total = (long long)ntiles * KTt;
    long long c        = (long long)blockIdx.x       * Total / PGRID;
    const long long c1 = (long long)(blockIdx.x + 1) * Total / PGRID;
    int* cnt = (EPI == 1) ? g_cnt1 : g_cnt2;

    while (c < c1){
        const int tile = (int)(c / KTt);
        const int ks   = (int)(c - (long long)tile * KTt);
        const int nk   = (int)min((long long)(KTt - ks), c1 - c);
        const int ke   = ks + nk;
        const int bm   = tile % ntm;
        const int bn   = tile / ntm;
        const float* Ag = AT + bm * 128;       // + k*M
        const float* Bg = Bw + bn * 128;       // + k*N

        unsigned long long acc[8][4];
        #pragma unroll
        for (int i = 0; i < 8; i++)
            #pragma unroll
            for (int j = 0; j < 4; j++) acc[i][j] = 0ull;

        auto ld_stage = [&](int kt, int s){
            uint32_t base = sbase + (uint32_t)(s * STAGE_F32) * 4;
            {   // A: 16 rows x 128 f32 = 512 16B chunks
                int ch = tid;
                #pragma unroll
                for (int i = 0; i < 2; i++, ch += 256){
                    int kl = ch >> 5, mc = ch & 31;
                    cp16(base + (uint32_t)(kl*128 + mc*4)*4,
                         Ag + (size_t)(kt*TK + kl)*M + mc*4);
                }
            }
            {   // B
                uint32_t bb = base + (uint32_t)(TK*128)*4;
                int ch = tid;
                #pragma unroll
                for (int i = 0; i < 2; i++, ch += 256){
                    int kl = ch >> 5, nc = ch & 31;
                    cp16(bb + (uint32_t)(kl*128 + nc*4)*4,
                         Bg + (size_t)(kt*TK + kl)*N + nc*4);
                }
            }
            asm volatile("cp.async.commit_group;" ::: "memory");
        };

        ld_stage(ks, 0);
        if (nk > 1) ld_stage(ks + 1, 1);

        int s = 0;
        for (int q = 0; q < nk; q++){
            if (q == nk - 1) asm volatile("cp.async.wait_group 0;" ::: "memory");
            else             asm volatile("cp.async.wait_group 1;" ::: "memory");
            __syncthreads();
            if (q + 2 < nk){
                int s2 = s + 2; if (s2 >= STAGES) s2 -= STAGES;
                ld_stage(ks + q + 2, s2);
            }

            const float* As = sm + s * STAGE_F32;
            const float* Bs = As + TK*128;

            // preload kk=0 fragments
            float4 a0 = *reinterpret_cast<const float4*>(As + ty*8);
            float4 a1 = *reinterpret_cast<const float4*>(As + ty*8 + 4);
            const unsigned long long* bq0 =
                reinterpret_cast<const unsigned long long*>(Bs + tx*4);
            const unsigned long long* bq1 =
                reinterpret_cast<const unsigned long long*>(Bs + tx*4 + 64);
            unsigned long long b0 = bq0[0], b1 = bq0[1], b2 = bq1[0], b3 = bq1[1];

            #pragma unroll
            for (int kk = 0; kk < TK; kk++){
                float4 na0, na1;
                unsigned long long nb0, nb1, nb2, nb3;
                if (kk + 1 < TK){
                    const float* Ar = As + (kk+1)*128;
                    const float* Br = Bs + (kk+1)*128;
                    na0 = *reinterpret_cast<const float4*>(Ar + ty*8);
                    na1 = *reinterpret_cast<const float4*>(Ar + ty*8 + 4);
                    const unsigned long long* p0 =
                        reinterpret_cast<const unsigned long long*>(Br + tx*4);
                    const unsigned long long* p1 =
                        reinterpret_cast<const unsigned long long*>(Br + tx*4 + 64);
                    nb0 = p0[0]; nb1 = p0[1]; nb2 = p1[0]; nb3 = p1[1];
                }
                float av[8] = {a0.x, a0.y, a0.z, a0.w, a1.x, a1.y, a1.z, a1.w};
                #pragma unroll
                for (int i = 0; i < 8; i++){
                    unsigned long long ap = pack2(av[i], av[i]);
                    ffma2(acc[i][0], ap, b0);
                    ffma2(acc[i][1], ap, b1);
                    ffma2(acc[i][2], ap, b2);
                    ffma2(acc[i][3], ap, b3);
                }
                if (kk + 1 < TK){
                    a0 = na0; a1 = na1;
                    b0 = nb0; b1 = nb1; b2 = nb2; b3 = nb3;
                }
            }
            s++; if (s >= STAGES) s = 0;
        }
        __syncthreads();    // smem buffers reused by the next tile's prologue

        if (ks > 0){
            // ---- contributor: write raw partial into this CTA's slot ----
            float* w = g_ws + (size_t)blockIdx.x * (64*256);
            #pragma unroll
            for (int i = 0; i < 8; i++)
                #pragma unroll
                for (int j = 0; j < 4; j++){
                    float2 u = unpack2(acc[i][j]);
                    int idx = (i*4 + j)*2;
                    w[(size_t)idx    *256 + tid] = u.x;
                    w[(size_t)(idx+1)*256 + tid] = u.y;
                }
            __threadfence();
            __syncthreads();
            if (tid == 0) atomicAdd(&cnt[tile], 1);
        } else {
            // ---- owner: merge any contributor partials (deterministic order) ----
            if (ke < KTt){
                long long tend = (long long)(tile + 1) * KTt;
                long long tstart = (long long)tile * KTt;
                int pfirst = -1, expect = 0;
                for (int p = blockIdx.x + 1; p < PGRID; p++){
                    long long pc0 = (long long)p * Total / PGRID;
                    if (pc0 >= tend) break;
                    if (pc0 > tstart){ if (!expect) pfirst = p; expect++; }
                }
                if (expect > 0){
                    if (tid == 0){
                        while (atomicAdd(&cnt[tile], 0) < expect) __nanosleep(100);
                    }
                    __syncthreads();
                    for (int p = pfirst; p < pfirst + expect; p++){
                        const float* w = g_ws + (size_t)p * (64*256);
                        #pragma unroll
                        for (int i = 0; i < 8; i++)
                            #pragma unroll
                            for (int j = 0; j < 4; j++){
                                int idx = (i*4 + j)*2;
                                float2 u = unpack2(acc[i][j]);
                                u.x += w[(size_t)idx    *256 + tid];
                                u.y += w[(size_t)(idx+1)*256 + tid];
                                acc[i][j] = pack2(u.x, u.y);
                            }
                    }
                }
            }

            // ---- full epilogue ----
            const int m0 = bm*128 + ty*8;
            const int n0a = bn*128 + tx*4;
            float bva[4], bvb[4];
            #pragma unroll
            for (int cc = 0; cc < 4; cc++){ bva[cc] = bias[n0a + cc]; bvb[cc] = bias[n0a + 64 + cc]; }

            if (EPI == 1){
                #pragma unroll
                for (int p = 0; p < 4; p++){
                    #pragma unroll
                    for (int h = 0; h < 2; h++){
                        int n = (p < 2) ? (n0a + p*2 + h) : (n0a + 64 + (p-2)*2 + h);
                        float bb = (p < 2) ? bva[p*2 + h] : bvb[(p-2)*2 + h];
                        float v[8];
                        #pragma unroll
                        for (int i = 0; i < 8; i++){
                            float2 u = unpack2(acc[i][p]);
                            v[i] = gelu_exact((h ? u.y : u.x) + bb);
                        }
                        float* dst = g_hT + (size_t)n * MROWS + m0;
                        *reinterpret_cast<float4*>(dst)     = make_float4(v[0], v[1], v[2], v[3]);
                        *reinterpret_cast<float4*>(dst + 4) = make_float4(v[4], v[5], v[6], v[7]);
                    }
                }
            } else {
                #pragma unroll
                for (int i = 0; i < 8; i++){
                    int m = m0 + i;
                    int bb = m >> 9;
                    int tok = g_tokens[m];
                    float wgt = g_rw[m];
                    size_t base = ((size_t)bb * Ssz + tok) * (size_t)Dd;
                    float2 q0 = unpack2(acc[i][0]), q1 = unpack2(acc[i][1]);
                    float2 q2 = unpack2(acc[i][2]), q3 = unpack2(acc[i][3]);
                    const float4 xa = *reinterpret_cast<const float4*>(xin + base + n0a);
                    const float4 xb = *reinterpret_cast<const float4*>(xin + base + n0a + 64);
                    float4 oa, ob;
                    oa.x = xa.x + wgt*(q0.x + bva[0]);  oa.y = xa.y + wgt*(q0.y + bva[1]);
                    oa.z = xa.z + wgt*(q1.x + bva[2]);  oa.w = xa.w + wgt*(q1.y + bva[3]);
                    ob.x = xb.x + wgt*(q2.x + bvb[0]);  ob.y = xb.y + wgt*(q2.y + bvb[1]);
                    ob.z = xb.z + wgt*(q3.x + bvb[2]);  ob.w = xb.w + wgt*(q3.y + bvb[3]);
                    *reinterpret_cast<float4*>(out + base + n0a)      = oa;
                    *reinterpret_cast<float4*>(out + base + n0a + 64) = ob;
                }
            }
        }
        c += nk;
    }
}

// ---------------- launch -------------------------------------------------------
extern "C" void kernel_launch(void* const* d_in, const int* in_sizes, int n_in,
                              void* d_out, int out_size){
    const float* x  = (const float*)d_in[0];
    const float* Wr = (const float*)d_in[1];
    const float* br = (const float*)d_in[2];
    const float* W1 = (const float*)d_in[3];
    const float* b1 = (const float*)d_in[4];
    const float* W2 = (const float*)d_in[5];
    const float* b2 = (const float*)d_in[6];
    float* out = (float*)d_out;

    cudaFuncSetAttribute(gemm_kernel<1>, cudaFuncAttributeMaxDynamicSharedMemorySize, SMEM_BYTES);
    cudaFuncSetAttribute(gemm_kernel<2>, cudaFuncAttributeMaxDynamicSharedMemorySize, SMEM_BYTES);

    router_kernel<<<(Bb*Ssz)/8, 256>>>(x, Wr, br);
    topk_copy_kernel<<<Bb + COPYB, 1024>>>(x, out);   // topk + hidden x->out copy
    gatherT_kernel<<<dim3(MROWS/32, Dd/32), 256>>>(x); // also zeroes stream-K counters

    float *p_fxT, *p_hT;
    cudaGetSymbolAddress((void**)&p_fxT, g_fxT);
    cudaGetSymbolAddress((void**)&p_hT,  g_hT);

    gemm_kernel<1><<<PGRID, 256, SMEM_BYTES>>>(
        p_fxT, W1, b1, nullptr, nullptr, MROWS, DFFz, Dd);
    gemm_kernel<2><<<PGRID, 256, SMEM_BYTES>>>(
        p_hT, W2, b2, x, out, MROWS, Dd, DFFz);
}